// round 16
// baseline (speedup 1.0000x reference)
#include <cuda_runtime.h>
#include <cuda_fp16.h>
#include <math.h>
#include <stdint.h>

// Problem constants (fixed by the reference)
#define Bsz   4096
#define INDIM 1024
#define Dm    512
#define Nn    8
#define Ss    128
#define HOPS  4
#define TILEM 64
#define MAXT  72      // max token tiles per hop: 4096/64 + 8

// packed-plane geometry (K dims packed by pairs into half2 words), K-slab = 64
#define A_ST2 36      // A smem stride (words): 36 mod 32 == 4 -> frag banks 4*lr+lc distinct
#define B_ST2 136     // B smem stride: 136 mod 32 == 8 -> frag banks 8*lc+lr distinct
// dynamic smem (words), tile 64(M) x 128(N), K-slab 64:
//   A stage s: hi [64][36] @ s*4608, lo @ +2304             (4608/stage)
//   B stage s: hi [32][136] @ 9216 + s*8704, lo @ +4352     (8704/stage)
#define SMEM_WORDS 26624
#define SMEM_BYTES (SMEM_WORDS * 4)   // 106496

// split_all ranges
#define NX    (Bsz * INDIM / 2)
#define NWIN  ((INDIM / 2) * Dm)
#define NSYM  (Nn * (Dm / 2) * Ss)
#define NOPS  (Nn * (Dm / 2) * Dm)
#define NALL  (NX + NWIN + NSYM + NOPS)

// -------- device scratch --------
__device__ float    g_z[Bsz * Dm];
__device__ float    g_symmean[Bsz * Ss];
__device__ int      g_prog[Bsz * HOPS];
__device__ int      g_order[HOPS][Bsz];
__device__ int      g_tileE[HOPS][MAXT];
__device__ int      g_tileS[HOPS][MAXT];
__device__ int      g_tileC[HOPS][MAXT];
__device__ int      g_numTiles[HOPS];
__device__ uint32_t g_xH[Bsz * INDIM / 2],  g_xL[Bsz * INDIM / 2];
__device__ uint32_t g_zH[Bsz * Dm / 2],     g_zL[Bsz * Dm / 2];
__device__ uint32_t g_bufH[Bsz * Dm / 2],   g_bufL[Bsz * Dm / 2];
__device__ uint32_t g_WinH[(INDIM / 2) * Dm],  g_WinL[(INDIM / 2) * Dm];
__device__ uint32_t g_symWH[Nn * (Dm / 2) * Ss], g_symWL[Nn * (Dm / 2) * Ss];
__device__ uint32_t g_opsWH[Nn * (Dm / 2) * Dm], g_opsWL[Nn * (Dm / 2) * Dm];

__device__ __forceinline__ float gelu_tanh(float x) {
    float x3 = x * x * x;
    return 0.5f * x * (1.0f + tanhf(0.7978845608028654f * (x + 0.044715f * x3)));
}
__device__ __forceinline__ void splitH(float v, __half& h, __half& l) {
    h = __float2half_rn(v);
    l = __float2half_rn(__fsub_rn(v, __half2float(h)));
}
__device__ __forceinline__ uint32_t packH(__half a, __half b) {
    __half2 p = __halves2half2(a, b);
    return *reinterpret_cast<uint32_t*>(&p);
}
__device__ __forceinline__ void two_sum(float a, float b, float& s, float& e) {
    s = __fadd_rn(a, b);
    float bv = __fsub_rn(s, a);
    e = __fadd_rn(__fsub_rn(a, __fsub_rn(s, bv)), __fsub_rn(b, bv));
}

#define MMAF16(d, a, b)                                                       \
    asm("mma.sync.aligned.m16n8k16.row.col.f32.f16.f16.f32 "                  \
        "{%0,%1,%2,%3}, {%4,%5,%6,%7}, {%8,%9}, {%0,%1,%2,%3};"               \
        : "+f"(d[0]), "+f"(d[1]), "+f"(d[2]), "+f"(d[3])                      \
        : "r"(a[0]), "r"(a[1]), "r"(a[2]), "r"(a[3]), "r"(b[0]), "r"(b[1]))

__device__ __forceinline__ void cp_async16(uint32_t saddr, const void* g) {
    asm volatile("cp.async.cg.shared.global [%0], [%1], 16;" :: "r"(saddr), "l"(g));
}
__device__ __forceinline__ void cp_async16_z(uint32_t saddr, const void* g, int srcsz) {
    asm volatile("cp.async.cg.shared.global [%0], [%1], 16, %2;"
                 :: "r"(saddr), "l"(g), "r"(srcsz));
}
#define CP_COMMIT() asm volatile("cp.async.commit_group;")
#define CP_WAIT0()  asm volatile("cp.async.wait_group 0;" ::: "memory")

// Stage A slab: 64 rows x 32 words, hi+lo planes. 256 threads, 4 cp16 each.
__device__ __forceinline__ void stage_A2(uint32_t* smem, int s,
                                         const uint32_t* __restrict__ GH,
                                         const uint32_t* __restrict__ GL,
                                         size_t row0, int ldw, int k2col, int tid) {
    const int plane = tid & 1;
    const int rr = tid >> 1;           // 0..127
    const int row = rr & 63;
    const int c0 = (rr >> 6) * 16;     // word col: 0 or 16
    const uint32_t* G = plane ? GL : GH;
    uint32_t base = (uint32_t)__cvta_generic_to_shared(smem + s * 4608 + plane * 2304);
    const uint32_t so = (uint32_t)(row * A_ST2 + c0) * 4;
    const uint32_t* src = G + (row0 + row) * ldw + k2col + c0;
    cp_async16(base + so,      src);
    cp_async16(base + so + 16, src + 4);
    cp_async16(base + so + 32, src + 8);
    cp_async16(base + so + 48, src + 12);
}

// Stage A with token gather (hop). tok<0 rows zero-filled.
__device__ __forceinline__ void stage_A2g(uint32_t* smem, int s,
                                          const uint32_t* __restrict__ GH,
                                          const uint32_t* __restrict__ GL,
                                          int tok, int k2col, int tid) {
    const int plane = tid & 1;
    const int rr = tid >> 1;
    const int row = rr & 63;
    const int c0 = (rr >> 6) * 16;
    const uint32_t* G = plane ? GL : GH;
    uint32_t base = (uint32_t)__cvta_generic_to_shared(smem + s * 4608 + plane * 2304);
    const uint32_t so = (uint32_t)(row * A_ST2 + c0) * 4;
    size_t grow = (size_t)(tok < 0 ? 0 : tok);
    int sz = tok < 0 ? 0 : 16;
    const uint32_t* src = G + grow * (Dm / 2) + k2col + c0;
    cp_async16_z(base + so,      src,      sz);
    cp_async16_z(base + so + 16, src + 4,  sz);
    cp_async16_z(base + so + 32, src + 8,  sz);
    cp_async16_z(base + so + 48, src + 12, sz);
}

// Stage B slab: 32 k2-rows x 128 n-words, hi+lo. 256 threads, 8 cp16 each.
__device__ __forceinline__ void stage_B2(uint32_t* smem, int s,
                                         const uint32_t* __restrict__ GH,
                                         const uint32_t* __restrict__ GL,
                                         size_t gbase, int ldw, int tid) {
    uint32_t base_h = (uint32_t)__cvta_generic_to_shared(smem + 9216 + s * 8704);
    uint32_t base_l = base_h + 4352 * 4;
#pragma unroll
    for (int p = 0; p < 4; p++) {
        int q = tid + p * 256;          // 0..1023
        int row = q >> 5, col = (q & 31) * 4;
        uint32_t soff = (uint32_t)(row * B_ST2 + col) * 4;
        size_t goff = gbase + (size_t)row * ldw + col;
        cp_async16(base_h + soff, GH + goff);
        cp_async16(base_l + soff, GL + goff);
    }
}

// One k16 step: warp (wm in 0..1, wn in 0..3) computes 32x32, 3xFP16.
__device__ __forceinline__ void mma_k16(
    const uint32_t* __restrict__ smem, int s, int wm, int wn, int lane, int k2off,
    float acc[2][4][4]) {
    const uint32_t* AhS = smem + s * 4608;
    const uint32_t* AlS = AhS + 2304;
    const uint32_t* BhS = smem + 9216 + s * 8704;
    const uint32_t* BlS = BhS + 4352;
    const int lr = lane >> 2, lc = lane & 3;
    uint32_t ah[2][4], al[2][4];
#pragma unroll
    for (int mt = 0; mt < 2; mt++) {
        int m = wm * 32 + mt * 16 + lr;
        ah[mt][0] = AhS[m * A_ST2 + k2off + lc];
        ah[mt][1] = AhS[(m + 8) * A_ST2 + k2off + lc];
        ah[mt][2] = AhS[m * A_ST2 + k2off + 4 + lc];
        ah[mt][3] = AhS[(m + 8) * A_ST2 + k2off + 4 + lc];
        al[mt][0] = AlS[m * A_ST2 + k2off + lc];
        al[mt][1] = AlS[(m + 8) * A_ST2 + k2off + lc];
        al[mt][2] = AlS[m * A_ST2 + k2off + 4 + lc];
        al[mt][3] = AlS[(m + 8) * A_ST2 + k2off + 4 + lc];
    }
#pragma unroll
    for (int nt = 0; nt < 4; nt++) {
        int n = wn * 32 + nt * 8 + lr;
        uint32_t bh[2], bl[2];
        bh[0] = BhS[(k2off + lc) * B_ST2 + n];
        bh[1] = BhS[(k2off + 4 + lc) * B_ST2 + n];
        bl[0] = BlS[(k2off + lc) * B_ST2 + n];
        bl[1] = BlS[(k2off + 4 + lc) * B_ST2 + n];
#pragma unroll
        for (int mt = 0; mt < 2; mt++) {
            MMAF16(acc[mt][nt], ah[mt], bl);
            MMAF16(acc[mt][nt], al[mt], bh);
            MMAF16(acc[mt][nt], ah[mt], bh);
        }
    }
}

// ============ zero g_symmean ============
__global__ void zero_mean() {
    int i = blockIdx.x * blockDim.x + threadIdx.x;
    reinterpret_cast<float4*>(g_symmean)[i] = make_float4(0.f, 0.f, 0.f, 0.f);
}

// ============ fused pre-split ============
__global__ void split_all(const float* __restrict__ x, const float* __restrict__ Win,
                          const float* __restrict__ symW, const float* __restrict__ opsW) {
    int i = blockIdx.x * blockDim.x + threadIdx.x;
    __half h0, l0, h1, l1;
    if (i < NX) {
        float2 v = reinterpret_cast<const float2*>(x)[i];
        splitH(v.x, h0, l0); splitH(v.y, h1, l1);
        g_xH[i] = packH(h0, h1);
        g_xL[i] = packH(l0, l1);
    } else if (i < NX + NWIN) {
        int j = i - NX;
        int r2 = j / Dm, c = j - r2 * Dm;
        float f0 = Win[(size_t)(2 * r2) * Dm + c];
        float f1 = Win[(size_t)(2 * r2 + 1) * Dm + c];
        splitH(f0, h0, l0); splitH(f1, h1, l1);
        g_WinH[j] = packH(h0, h1);
        g_WinL[j] = packH(l0, l1);
    } else if (i < NX + NWIN + NSYM) {
        int j = i - NX - NWIN;
        int r2 = j / Ss, c = j - r2 * Ss;
        float f0 = symW[(size_t)(2 * r2) * Ss + c];
        float f1 = symW[(size_t)(2 * r2 + 1) * Ss + c];
        splitH(f0, h0, l0); splitH(f1, h1, l1);
        g_symWH[j] = packH(h0, h1);
        g_symWL[j] = packH(l0, l1);
    } else {
        int j = i - NX - NWIN - NSYM;
        int r2 = j / Dm, c = j - r2 * Dm;
        float f0 = opsW[(size_t)(2 * r2) * Dm + c];
        float f1 = opsW[(size_t)(2 * r2 + 1) * Dm + c];
        splitH(f0, h0, l0); splitH(f1, h1, l1);
        g_opsWH[j] = packH(h0, h1);
        g_opsWL[j] = packH(l0, l1);
    }
}

// ============ GEMM 1: z = x @ W_in + b_in (tile 64x128, K-slab 64) ============
__global__ __launch_bounds__(256) void gemm_z_tc(const float* __restrict__ bias) {
    extern __shared__ uint32_t smem[];
    const int tid = threadIdx.x, lane = tid & 31, warp = tid >> 5;
    const int wm = warp & 1, wn = warp >> 1;
    const size_t bm = blockIdx.x * TILEM;
    const int bn = blockIdx.y * 128;
    float acc[2][4][4] = {};
    stage_A2(smem, 0, g_xH, g_xL, bm, INDIM / 2, 0, tid);
    stage_B2(smem, 0, g_WinH, g_WinL, (size_t)bn, Dm, tid);
    CP_COMMIT();
    stage_A2(smem, 1, g_xH, g_xL, bm, INDIM / 2, 32, tid);
    stage_B2(smem, 1, g_WinH, g_WinL, (size_t)32 * Dm + bn, Dm, tid);
    CP_COMMIT();
    for (int k0 = 0; k0 < INDIM; k0 += 64) {
        const int s = (k0 >> 6) & 1;
        asm volatile("cp.async.wait_group 1;" ::: "memory");
        __syncthreads();
        mma_k16(smem, s, wm, wn, lane, 0, acc);
        mma_k16(smem, s, wm, wn, lane, 8, acc);
        mma_k16(smem, s, wm, wn, lane, 16, acc);
        mma_k16(smem, s, wm, wn, lane, 24, acc);
        __syncthreads();
        if (k0 + 128 < INDIM) {
            stage_A2(smem, s, g_xH, g_xL, bm, INDIM / 2, (k0 + 128) / 2, tid);
            stage_B2(smem, s, g_WinH, g_WinL, (size_t)((k0 + 128) / 2) * Dm + bn, Dm, tid);
        }
        CP_COMMIT();
    }
    const int lr = lane >> 2, lc = lane & 3;
#pragma unroll
    for (int mt = 0; mt < 2; mt++)
#pragma unroll
        for (int nt = 0; nt < 4; nt++) {
            size_t m0 = bm + wm * 32 + mt * 16 + lr;
            int n0 = bn + wn * 32 + nt * 8 + 2 * lc;
            float b0 = bias[n0], b1 = bias[n0 + 1];
            float v00 = acc[mt][nt][0] + b0, v01 = acc[mt][nt][1] + b1;
            float v10 = acc[mt][nt][2] + b0, v11 = acc[mt][nt][3] + b1;
            g_z[m0 * Dm + n0] = v00;           g_z[m0 * Dm + n0 + 1] = v01;
            g_z[(m0 + 8) * Dm + n0] = v10;     g_z[(m0 + 8) * Dm + n0 + 1] = v11;
            __half h0, l0, h1, l1;
            splitH(v00, h0, l0); splitH(v01, h1, l1);
            g_zH[m0 * (Dm / 2) + n0 / 2] = packH(h0, h1);
            g_zL[m0 * (Dm / 2) + n0 / 2] = packH(l0, l1);
            splitH(v10, h0, l0); splitH(v11, h1, l1);
            g_zH[(m0 + 8) * (Dm / 2) + n0 / 2] = packH(h0, h1);
            g_zL[(m0 + 8) * (Dm / 2) + n0 / 2] = packH(l0, l1);
        }
}

// ======= GEMM 2: sym = z @ sym_W + fused mean (tile 64x128, K-slab 64) =======
__global__ __launch_bounds__(256) void gemm_sym_tc(float* __restrict__ symOut) {
    extern __shared__ uint32_t smem[];
    const int tid = threadIdx.x, lane = tid & 31, warp = tid >> 5;
    const int wm = warp & 1, wn = warp >> 1;
    const size_t bm = blockIdx.x * TILEM;
    const int bn = blockIdx.y * 128;
    const size_t boff = (size_t)blockIdx.y * ((Dm / 2) * Ss);
    float acc[2][4][4] = {};
    stage_A2(smem, 0, g_zH, g_zL, bm, Dm / 2, 0, tid);
    stage_B2(smem, 0, g_symWH, g_symWL, boff, Ss, tid);
    CP_COMMIT();
    stage_A2(smem, 1, g_zH, g_zL, bm, Dm / 2, 32, tid);
    stage_B2(smem, 1, g_symWH, g_symWL, boff + (size_t)32 * Ss, Ss, tid);
    CP_COMMIT();
    for (int k0 = 0; k0 < Dm; k0 += 64) {
        const int s = (k0 >> 6) & 1;
        asm volatile("cp.async.wait_group 1;" ::: "memory");
        __syncthreads();
        mma_k16(smem, s, wm, wn, lane, 0, acc);
        mma_k16(smem, s, wm, wn, lane, 8, acc);
        mma_k16(smem, s, wm, wn, lane, 16, acc);
        mma_k16(smem, s, wm, wn, lane, 24, acc);
        __syncthreads();
        if (k0 + 128 < Dm) {
            stage_A2(smem, s, g_zH, g_zL, bm, Dm / 2, (k0 + 128) / 2, tid);
            stage_B2(smem, s, g_symWH, g_symWL,
                     boff + (size_t)((k0 + 128) / 2) * Ss, Ss, tid);
        }
        CP_COMMIT();
    }
    const int lr = lane >> 2, lc = lane & 3;
#pragma unroll
    for (int mt = 0; mt < 2; mt++)
#pragma unroll
        for (int nt = 0; nt < 4; nt++) {
            size_t m0 = bm + wm * 32 + mt * 16 + lr;
            int n0 = bn + wn * 32 + nt * 8 + 2 * lc;
            int sc = wn * 32 + nt * 8 + 2 * lc;
            float v00 = acc[mt][nt][0], v01 = acc[mt][nt][1];
            float v10 = acc[mt][nt][2], v11 = acc[mt][nt][3];
            symOut[m0 * (Nn * Ss) + n0]           = v00;
            symOut[m0 * (Nn * Ss) + n0 + 1]       = v01;
            symOut[(m0 + 8) * (Nn * Ss) + n0]     = v10;
            symOut[(m0 + 8) * (Nn * Ss) + n0 + 1] = v11;
            atomicAdd(&g_symmean[m0 * Ss + sc],           0.125f * v00);
            atomicAdd(&g_symmean[m0 * Ss + sc + 1],       0.125f * v01);
            atomicAdd(&g_symmean[(m0 + 8) * Ss + sc],     0.125f * v10);
            atomicAdd(&g_symmean[(m0 + 8) * Ss + sc + 1], 0.125f * v11);
        }
}

// ====== router: compensated-fp32 split-k x4 + exact merge; argmax -> prog ======
__global__ __launch_bounds__(576) void router_kernel(
    const float* __restrict__ RW, const float* __restrict__ rb, float* __restrict__ progf) {
    __shared__ float rin[4][644];
    __shared__ float ps[4][36][4], pc[4][36][4];
    __shared__ float lg[4][36];
    const int b0 = blockIdx.x * 4;
    const int tid = threadIdx.x;
    for (int i = tid; i < 4 * 640; i += 576) {
        int t = i / 640, k = i - t * 640;
        rin[t][k] = (k < Dm) ? g_z[(size_t)(b0 + t) * Dm + k]
                             : g_symmean[(size_t)(b0 + t) * Ss + (k - Dm)];
    }
    __syncthreads();
    {
        const int t  = tid / 144;
        const int r  = tid - t * 144;
        const int j  = r % 36;
        const int ks = r / 36;
        const int kbeg = ks * 160;
        const float* rw = RW + j;
        float s0 = 0.f, s1 = 0.f, c0 = 0.f, c1 = 0.f;
#pragma unroll 4
        for (int k = kbeg; k < kbeg + 160; k += 2) {
            {
                float x = rin[t][k];
                float w = __ldg(&rw[k * 36]);
                float p = __fmul_rn(x, w);
                float e = __fmaf_rn(x, w, -p);
                float S, er; two_sum(s0, p, S, er);
                s0 = S; c0 = __fadd_rn(c0, __fadd_rn(er, e));
            }
            {
                float x = rin[t][k + 1];
                float w = __ldg(&rw[(k + 1) * 36]);
                float p = __fmul_rn(x, w);
                float e = __fmaf_rn(x, w, -p);
                float S, er; two_sum(s1, p, S, er);
                s1 = S; c1 = __fadd_rn(c1, __fadd_rn(er, e));
            }
        }
        float S, er; two_sum(s0, s1, S, er);
        ps[t][j][ks] = S;
        pc[t][j][ks] = __fadd_rn(c0, __fadd_rn(c1, er));
    }
    __syncthreads();
    if (tid < 144) {
        int t = tid / 36, j = tid - t * 36;
        float S = ps[t][j][0], C = pc[t][j][0];
#pragma unroll
        for (int ks = 1; ks < 4; ks++) {
            float S2, er; two_sum(S, ps[t][j][ks], S2, er);
            S = S2;
            C = __fadd_rn(C, __fadd_rn(er, pc[t][j][ks]));
        }
        float S2, er; two_sum(S, rb[j], S2, er);
        lg[t][j] = __fadd_rn(S2, __fadd_rn(C, er));
    }
    __syncthreads();
    if (tid < 16) {
        int t = tid >> 2, h = tid & 3;
        const float* l = &lg[t][h * 9];
        float best = l[0]; int bi = 0;
#pragma unroll
        for (int j = 1; j < 9; j++)
            if (l[j] > best) { best = l[j]; bi = j; }
        g_prog[(b0 + t) * HOPS + h] = bi;
        progf[(b0 + t) * HOPS + h] = (float)bi;
    }
}

// ======= schedule: group active tokens by (hop, expert); 64-row tiles =======
__global__ void schedule_kernel() {
    __shared__ int cnt[HOPS][Nn];
    __shared__ int cur[HOPS][Nn];
    const int tid = threadIdx.x;
    if (tid < HOPS * Nn) cnt[tid / Nn][tid % Nn] = 0;
    __syncthreads();
    for (int b = tid; b < Bsz; b += blockDim.x) {
        bool act = true;
        for (int t = 0; t < HOPS; t++) {
            int e = g_prog[b * HOPS + t];
            act = act && (e != Nn);
            if (act) atomicAdd(&cnt[t][e], 1);
        }
    }
    __syncthreads();
    if (tid < HOPS) {
        int t = tid, p = 0, nt = 0;
        for (int e = 0; e < Nn; e++) {
            cur[t][e] = p;
            int c = cnt[t][e], q = p;
            while (c > 0) {
                g_tileE[t][nt] = e; g_tileS[t][nt] = q;
                g_tileC[t][nt] = (c < TILEM) ? c : TILEM;
                q += TILEM; c -= TILEM; nt++;
            }
            p += cnt[t][e];
        }
        g_numTiles[t] = nt;
    }
    __syncthreads();
    for (int b = tid; b < Bsz; b += blockDim.x) {
        bool act = true;
        for (int t = 0; t < HOPS; t++) {
            int e = g_prog[b * HOPS + t];
            act = act && (e != Nn);
            if (act) { int p = atomicAdd(&cur[t][e], 1); g_order[t][p] = b; }
        }
    }
}

// == hop: dst planes[tok] = split(gelu(src[tok] @ ops_W[e] + b)), tile 64x128, K-slab 64 ==
__global__ __launch_bounds__(256) void hop_tc(
    int hop, int srcSel, const float* __restrict__ opsB) {
    if ((int)blockIdx.x >= g_numTiles[hop]) return;
    extern __shared__ uint32_t smem[];
    __shared__ int toks[TILEM];
    const uint32_t* srcH = (srcSel == 0) ? g_zH : g_bufH;
    const uint32_t* srcL = (srcSel == 0) ? g_zL : g_bufL;
    uint32_t* dstH = (srcSel == 0) ? g_bufH : g_zH;
    uint32_t* dstL = (srcSel == 0) ? g_bufL : g_zL;
    const int e     = g_tileE[hop][blockIdx.x];
    const int start = g_tileS[hop][blockIdx.x];
    const int cnt   = g_tileC[hop][blockIdx.x];
    const int bn    = blockIdx.y * 128;
    const int tid = threadIdx.x, lane = tid & 31, warp = tid >> 5;
    const int wm = warp & 1, wn = warp >> 1;
    if (tid < TILEM) toks[tid] = (tid < cnt) ? g_order[hop][start + tid] : -1;
    __syncthreads();
    const uint32_t* WH = g_opsWH + (size_t)e * ((Dm / 2) * Dm);
    const uint32_t* WL = g_opsWL + (size_t)e * ((Dm / 2) * Dm);
    const int myTok = toks[(tid >> 1) & 63];
    stage_A2g(smem, 0, srcH, srcL, myTok, 0, tid);
    stage_B2(smem, 0, WH, WL, (size_t)bn, Dm, tid);
    CP_COMMIT();
    stage_A2g(smem, 1, srcH, srcL, myTok, 32, tid);
    stage_B2(smem, 1, WH, WL, (size_t)32 * Dm + bn, Dm, tid);
    CP_COMMIT();
    float acc[2][4][4] = {};
    for (int k0 = 0; k0 < Dm; k0 += 64) {
        const int s = (k0 >> 6) & 1;
        asm volatile("cp.async.wait_group 1;" ::: "memory");
        __syncthreads();
        mma_k16(smem, s, wm, wn, lane, 0, acc);
        mma_k16(smem, s, wm, wn, lane, 8, acc);
        mma_k16(smem, s, wm, wn, lane, 16, acc);
        mma_k16(smem, s, wm, wn, lane, 24, acc);
        __syncthreads();
        if (k0 + 128 < Dm) {
            stage_A2g(smem, s, srcH, srcL, myTok, (k0 + 128) / 2, tid);
            stage_B2(smem, s, WH, WL, (size_t)((k0 + 128) / 2) * Dm + bn, Dm, tid);
        }
        CP_COMMIT();
    }
    const int lr = lane >> 2, lc = lane & 3;
#pragma unroll
    for (int mt = 0; mt < 2; mt++) {
        int r0 = wm * 32 + mt * 16 + lr;
        int tk0 = toks[r0], tk1 = toks[r0 + 8];
#pragma unroll
        for (int nt = 0; nt < 4; nt++) {
            int n0 = bn + wn * 32 + nt * 8 + 2 * lc;
            float b0 = opsB[e * Dm + n0], b1 = opsB[e * Dm + n0 + 1];
            if (tk0 >= 0) {
                float v0 = gelu_tanh(acc[mt][nt][0] + b0);
                float v1 = gelu_tanh(acc[mt][nt][1] + b1);
                __half h0, l0, h1, l1;
                splitH(v0, h0, l0); splitH(v1, h1, l1);
                dstH[(size_t)tk0 * (Dm / 2) + n0 / 2] = packH(h0, h1);
                dstL[(size_t)tk0 * (Dm / 2) + n0 / 2] = packH(l0, l1);
            }
            if (tk1 >= 0) {
                float v0 = gelu_tanh(acc[mt][nt][2] + b0);
                float v1 = gelu_tanh(acc[mt][nt][3] + b1);
                __half h0, l0, h1, l1;
                splitH(v0, h0, l0); splitH(v1, h1, l1);
                dstH[(size_t)tk1 * (Dm / 2) + n0 / 2] = packH(h0, h1);
                dstL[(size_t)tk1 * (Dm / 2) + n0 / 2] = packH(l0, l1);
            }
        }
    }
}

// ===== final gather =====
__global__ void gather_out(float* __restrict__ out) {
    int idx = blockIdx.x * blockDim.x + threadIdx.x;
    int b = idx >> 8;
    int nact = 0;
#pragma unroll
    for (int t = 0; t < HOPS; t++) {
        if (g_prog[b * HOPS + t] == Nn) break;
        nact++;
    }
    const uint32_t* sH = (nact & 1) ? g_bufH : g_zH;
    const uint32_t* sL = (nact & 1) ? g_bufL : g_zL;
    uint32_t wh = sH[idx], wl = sL[idx];
    __half2 h = *reinterpret_cast<__half2*>(&wh);
    __half2 l = *reinterpret_cast<__half2*>(&wl);
    float2 o;
    o.x = __fadd_rn(__half2float(__low2half(h)),  __half2float(__low2half(l)));
    o.y = __fadd_rn(__half2float(__high2half(h)), __half2float(__high2half(l)));
    reinterpret_cast<float2*>(out)[idx] = o;
}

// =========================== launch ===========================
extern "C" void kernel_launch(void* const* d_in, const int* in_sizes, int n_in,
                              void* d_out, int out_size) {
    const float* x        = (const float*)d_in[0];
    const float* W_in     = (const float*)d_in[1];
    const float* b_in     = (const float*)d_in[2];
    const float* ops_W    = (const float*)d_in[3];
    const float* ops_b    = (const float*)d_in[4];
    const float* sym_W    = (const float*)d_in[5];
    const float* router_W = (const float*)d_in[6];
    const float* router_b = (const float*)d_in[7];
    (void)in_sizes; (void)n_in; (void)out_size;

    float* out   = (float*)d_out;
    float* progf = out + Bsz * Dm;
    float* sym   = progf + Bsz * HOPS;

    cudaFuncSetAttribute(gemm_z_tc,   cudaFuncAttributeMaxDynamicSharedMemorySize, SMEM_BYTES);
    cudaFuncSetAttribute(gemm_sym_tc, cudaFuncAttributeMaxDynamicSharedMemorySize, SMEM_BYTES);
    cudaFuncSetAttribute(hop_tc,      cudaFuncAttributeMaxDynamicSharedMemorySize, SMEM_BYTES);

    zero_mean <<<(Bsz * Ss / 4) / 256, 256>>>();
    split_all <<<NALL / 256, 256>>>(x, W_in, sym_W, ops_W);

    gemm_z_tc   <<<dim3(Bsz / TILEM, Dm / 128), 256, SMEM_BYTES>>>(b_in);
    gemm_sym_tc <<<dim3(Bsz / TILEM, (Nn * Ss) / 128), 256, SMEM_BYTES>>>(sym);  // 4th: profiled
    router_kernel<<<Bsz / 4, 576>>>(router_W, router_b, progf);
    schedule_kernel<<<1, 512>>>();

    hop_tc<<<dim3(MAXT, Dm / 128), 256, SMEM_BYTES>>>(0, 0, ops_b);
    hop_tc<<<dim3(MAXT, Dm / 128), 256, SMEM_BYTES>>>(1, 1, ops_b);
    hop_tc<<<dim3(MAXT, Dm / 128), 256, SMEM_BYTES>>>(2, 0, ops_b);
    hop_tc<<<dim3(MAXT, Dm / 128), 256, SMEM_BYTES>>>(3, 1, ops_b);

    gather_out<<<(Bsz * Dm / 2) / 256, 256>>>(out);
}